// round 1
// baseline (speedup 1.0000x reference)
#include <cuda_runtime.h>
#include <cuda_bf16.h>
#include <cstdint>

// out[b,k] = log( sum_n exp(x[b,n]) * exp(acc[n,k]) ) - log( sum_n exp(acc[n,k]) )
// per (s,d) batch: GEMM M=128 (batch), N=512 (sums), K=512 (nodes_in)

#define NSD     256     // S*D
#define BDIM    128
#define NIN     512
#define NSUM    512
#define KC      32      // K chunk per iteration
#define NT      64      // N tile per CTA
#define APITCH  40      // bf16 elems per A smem row (32 + 8 pad) -> 20 words, conflict-free a-frags
#define BPITCH  72      // bf16 elems per B smem row (64 + 8 pad)

__device__ __forceinline__ unsigned packbf(float a, float b) {
    __nv_bfloat162 h = __floats2bfloat162_rn(a, b);
    return *reinterpret_cast<unsigned const*>(&h);
}

__global__ __launch_bounds__(256, 2) void densesum_kernel(
    const float* __restrict__ X,   // [NSD][BDIM][NIN]
    const float* __restrict__ W,   // [NSD][NIN][NSUM]
    float* __restrict__ O)         // [NSD][BDIM][NSUM]
{
    const int ct = blockIdx.x;     // N tile index, 0..7
    const int sd = blockIdx.y;     // 0..255

    const float* Xp = X + (size_t)sd * BDIM * NIN;
    const float* Wp = W + (size_t)sd * NIN * NSUM + ct * NT;
    float*       Op = O + (size_t)sd * BDIM * NSUM + ct * NT;

    __shared__ __align__(16) __nv_bfloat16 As[2][BDIM * APITCH];
    __shared__ __align__(16) __nv_bfloat16 Bs[2][KC * BPITCH];
    __shared__ float csums[NT];

    const int t = threadIdx.x;
    if (t < NT) csums[t] = 0.f;

    const int warp = t >> 5, lane = t & 31;
    const int wm = warp >> 1;      // 0..3  (M position, 32 rows each)
    const int wn = warp & 1;       // 0..1  (N position, 32 cols each)
    const int g  = lane >> 2;      // 0..7
    const int q  = lane & 3;       // 0..3

    // Gmem load mapping (fixed per thread):
    // A: rows ar+32j (j<4), 4 consecutive cols at ac.   B: rows br+16j (j<2), cols bc..bc+3
    const int ar = t >> 3;
    const int ac = (t & 7) * 4;
    const int br = t >> 4;
    const int bc = (t & 15) * 4;

    float acc[2][4][4];
    #pragma unroll
    for (int i = 0; i < 2; i++)
        #pragma unroll
        for (int j = 0; j < 4; j++)
            #pragma unroll
            for (int k = 0; k < 4; k++) acc[i][j][k] = 0.f;

    float csum[4] = {0.f, 0.f, 0.f, 0.f};

    // prefetch chunk 0
    float4 pa[4], pb[2];
    #pragma unroll
    for (int j = 0; j < 4; j++)
        pa[j] = *reinterpret_cast<const float4*>(Xp + (size_t)(ar + 32 * j) * NIN + ac);
    #pragma unroll
    for (int j = 0; j < 2; j++)
        pb[j] = *reinterpret_cast<const float4*>(Wp + (size_t)(br + 16 * j) * NSUM + bc);

    const int NCH = NIN / KC;  // 16
    for (int ch = 0; ch < NCH; ch++) {
        const int buf = ch & 1;

        // exp + bf16 convert + STS (A tile)
        #pragma unroll
        for (int j = 0; j < 4; j++) {
            float4 v = pa[j];
            uint2 u = make_uint2(packbf(__expf(v.x), __expf(v.y)),
                                 packbf(__expf(v.z), __expf(v.w)));
            *reinterpret_cast<uint2*>(&As[buf][(ar + 32 * j) * APITCH + ac]) = u;
        }
        // exp + bf16 convert + STS (B tile), plus column-sum accumulation
        #pragma unroll
        for (int j = 0; j < 2; j++) {
            float4 v = pb[j];
            float e0 = __expf(v.x), e1 = __expf(v.y), e2 = __expf(v.z), e3 = __expf(v.w);
            csum[0] += e0; csum[1] += e1; csum[2] += e2; csum[3] += e3;
            uint2 u = make_uint2(packbf(e0, e1), packbf(e2, e3));
            *reinterpret_cast<uint2*>(&Bs[buf][(br + 16 * j) * BPITCH + bc]) = u;
        }
        __syncthreads();

        // prefetch next chunk while MMAs run
        if (ch + 1 < NCH) {
            const float* Xn = Xp + (ch + 1) * KC;
            const float* Wn = Wp + (size_t)(ch + 1) * KC * NSUM;
            #pragma unroll
            for (int j = 0; j < 4; j++)
                pa[j] = *reinterpret_cast<const float4*>(Xn + (size_t)(ar + 32 * j) * NIN + ac);
            #pragma unroll
            for (int j = 0; j < 2; j++)
                pb[j] = *reinterpret_cast<const float4*>(Wn + (size_t)(br + 16 * j) * NSUM + bc);
        }

        // MMA over this chunk (two k16 steps)
        const unsigned*       Aw = reinterpret_cast<const unsigned*>(&As[buf][0]);
        const unsigned short* Bb = reinterpret_cast<const unsigned short*>(&Bs[buf][0]);
        #pragma unroll
        for (int ks = 0; ks < 2; ks++) {
            unsigned afr[2][4];
            #pragma unroll
            for (int mf = 0; mf < 2; mf++) {
                const int r0 = wm * 32 + mf * 16 + g;
                const int base = ks * 8 + q;           // word offset within row (20-word pitch)
                afr[mf][0] = Aw[r0 * (APITCH / 2) + base];
                afr[mf][1] = Aw[(r0 + 8) * (APITCH / 2) + base];
                afr[mf][2] = Aw[r0 * (APITCH / 2) + base + 4];
                afr[mf][3] = Aw[(r0 + 8) * (APITCH / 2) + base + 4];
            }
            unsigned bfr[4][2];
            #pragma unroll
            for (int nf = 0; nf < 4; nf++) {
                const int c  = wn * 32 + nf * 8 + g;
                const int r0 = ks * 16 + q * 2;
                unsigned lo0 = Bb[r0 * BPITCH + c];
                unsigned hi0 = Bb[(r0 + 1) * BPITCH + c];
                bfr[nf][0] = lo0 | (hi0 << 16);
                unsigned lo1 = Bb[(r0 + 8) * BPITCH + c];
                unsigned hi1 = Bb[(r0 + 9) * BPITCH + c];
                bfr[nf][1] = lo1 | (hi1 << 16);
            }
            #pragma unroll
            for (int mf = 0; mf < 2; mf++)
                #pragma unroll
                for (int nf = 0; nf < 4; nf++) {
                    asm volatile(
                        "mma.sync.aligned.m16n8k16.row.col.f32.bf16.bf16.f32 "
                        "{%0,%1,%2,%3}, {%4,%5,%6,%7}, {%8,%9}, {%0,%1,%2,%3};\n"
                        : "+f"(acc[mf][nf][0]), "+f"(acc[mf][nf][1]),
                          "+f"(acc[mf][nf][2]), "+f"(acc[mf][nf][3])
                        : "r"(afr[mf][0]), "r"(afr[mf][1]),
                          "r"(afr[mf][2]), "r"(afr[mf][3]),
                          "r"(bfr[nf][0]), "r"(bfr[nf][1]));
                }
        }
        // double-buffered: the barrier above already protects buf^1 for next iter's STS
    }

    // reduce per-thread column sums (threads sharing bc cover disjoint n rows)
    atomicAdd(&csums[bc + 0], csum[0]);
    atomicAdd(&csums[bc + 1], csum[1]);
    atomicAdd(&csums[bc + 2], csum[2]);
    atomicAdd(&csums[bc + 3], csum[3]);
    __syncthreads();

    // epilogue: out = log(P) - log(C[col])
    #pragma unroll
    for (int nf = 0; nf < 4; nf++) {
        const int c = wn * 32 + nf * 8 + q * 2;
        const float lc0 = __logf(csums[c]);
        const float lc1 = __logf(csums[c + 1]);
        #pragma unroll
        for (int mf = 0; mf < 2; mf++) {
            const int r0 = wm * 32 + mf * 16 + g;
            Op[(size_t)r0 * NSUM + c]           = __logf(acc[mf][nf][0]) - lc0;
            Op[(size_t)r0 * NSUM + c + 1]       = __logf(acc[mf][nf][1]) - lc1;
            Op[(size_t)(r0 + 8) * NSUM + c]     = __logf(acc[mf][nf][2]) - lc0;
            Op[(size_t)(r0 + 8) * NSUM + c + 1] = __logf(acc[mf][nf][3]) - lc1;
        }
    }
}

extern "C" void kernel_launch(void* const* d_in, const int* in_sizes, int n_in,
                              void* d_out, int out_size)
{
    const float* x   = (const float*)d_in[0];
    const float* accs = (const float*)d_in[1];
    // defensive: x is 16.8M elems, accumulators 67.1M — swap if metadata order differs
    if (n_in >= 2 && in_sizes[0] > in_sizes[1]) {
        const float* tmp = x; x = accs; accs = tmp;
    }
    dim3 grid(NSUM / NT, NSD);   // (8, 256)
    densesum_kernel<<<grid, 256>>>(x, accs, (float*)d_out);
}

// round 3
// speedup vs baseline: 1.0416x; 1.0416x over previous
#include <cuda_runtime.h>
#include <cuda_bf16.h>
#include <cstdint>

// out[b,k] = log( sum_n exp(x[b,n]) * exp(acc[n,k]) ) - log( sum_n exp(acc[n,k]) )
// per (s,d) batch: GEMM M=128 (batch), N=512 (sums), K=512 (nodes_in)
// bf16 HMMA (mma.m16n8k16) with ldmatrix fragment loads.

#define NSD     256     // S*D
#define BDIM    128
#define NIN     512
#define NSUM    512
#define KC      32      // K chunk per iteration
#define NT      64      // N tile per CTA
#define APITCH  40      // bf16/row: 80B stride -> LDSM conflict-free (20i mod 32 distinct)
#define BPITCH  72      // bf16/row: 144B stride -> LDSM conflict-free (4i mod 32 distinct)

__device__ __forceinline__ unsigned packbf(float a, float b) {
    __nv_bfloat162 h = __floats2bfloat162_rn(a, b);
    return *reinterpret_cast<unsigned const*>(&h);
}

__device__ __forceinline__ uint32_t s2u(const void* p) {
    uint32_t a;
    asm("{ .reg .u64 t; cvta.to.shared.u64 t, %1; cvt.u32.u64 %0, t; }" : "=r"(a) : "l"(p));
    return a;
}

__global__ __launch_bounds__(256, 2) void densesum_kernel(
    const float* __restrict__ X,   // [NSD][BDIM][NIN]
    const float* __restrict__ W,   // [NSD][NIN][NSUM]
    float* __restrict__ O)         // [NSD][BDIM][NSUM]
{
    const int ct = blockIdx.x;     // N tile index, 0..7
    const int sd = blockIdx.y;     // 0..255

    const float* Xp = X + (size_t)sd * BDIM * NIN;
    const float* Wp = W + (size_t)sd * NIN * NSUM + ct * NT;
    float*       Op = O + (size_t)sd * BDIM * NSUM + ct * NT;

    __shared__ __align__(16) __nv_bfloat16 As[2][BDIM * APITCH];
    __shared__ __align__(16) __nv_bfloat16 Bs[2][KC * BPITCH];
    __shared__ float csums[NT];

    const int t = threadIdx.x;
    if (t < NT) csums[t] = 0.f;

    const int warp = t >> 5, lane = t & 31;
    const int wm = warp >> 1;      // 0..3  (M position, 32 rows each)
    const int wn = warp & 1;       // 0..1  (N position, 32 cols each)
    const int l15 = lane & 15;
    const int lhi = lane >> 4;     // 0/1

    // Gmem load mapping (fixed per thread):
    const int ar = t >> 3;
    const int ac = (t & 7) * 4;
    const int br = t >> 4;
    const int bc = (t & 15) * 4;

    // ldmatrix per-lane base byte offsets (within a buffer)
    // A x4: lane -> row (wm*32 + mf*16 + l15), col (ks*16 + lhi*8)
    const uint32_t As0 = s2u(&As[0][0]);
    const uint32_t Bs0 = s2u(&Bs[0][0]);
    const uint32_t aln = (uint32_t)((wm * 32 + l15) * APITCH + lhi * 8) * 2;
    // B x4.trans: lane -> row (ks*16 + l15), col (wn*32 + npair*16 + lhi*8)
    const uint32_t bln = (uint32_t)(l15 * BPITCH + wn * 32 + lhi * 8) * 2;

    float acc[2][4][4];
    #pragma unroll
    for (int i = 0; i < 2; i++)
        #pragma unroll
        for (int j = 0; j < 4; j++)
            #pragma unroll
            for (int k = 0; k < 4; k++) acc[i][j][k] = 0.f;

    float csum[4] = {0.f, 0.f, 0.f, 0.f};

    // prefetch chunk 0
    float4 pa[4], pb[2];
    #pragma unroll
    for (int j = 0; j < 4; j++)
        pa[j] = *reinterpret_cast<const float4*>(Xp + (size_t)(ar + 32 * j) * NIN + ac);
    #pragma unroll
    for (int j = 0; j < 2; j++)
        pb[j] = *reinterpret_cast<const float4*>(Wp + (size_t)(br + 16 * j) * NSUM + bc);

    const int NCH = NIN / KC;  // 16
    for (int ch = 0; ch < NCH; ch++) {
        const int buf = ch & 1;

        // exp + bf16 convert + STS (A tile)
        #pragma unroll
        for (int j = 0; j < 4; j++) {
            float4 v = pa[j];
            uint2 u = make_uint2(packbf(__expf(v.x), __expf(v.y)),
                                 packbf(__expf(v.z), __expf(v.w)));
            *reinterpret_cast<uint2*>(&As[buf][(ar + 32 * j) * APITCH + ac]) = u;
        }
        // exp + bf16 convert + STS (B tile), plus column-sum accumulation
        #pragma unroll
        for (int j = 0; j < 2; j++) {
            float4 v = pb[j];
            float e0 = __expf(v.x), e1 = __expf(v.y), e2 = __expf(v.z), e3 = __expf(v.w);
            csum[0] += e0; csum[1] += e1; csum[2] += e2; csum[3] += e3;
            uint2 u = make_uint2(packbf(e0, e1), packbf(e2, e3));
            *reinterpret_cast<uint2*>(&Bs[buf][(br + 16 * j) * BPITCH + bc]) = u;
        }
        __syncthreads();

        // prefetch next chunk while MMAs run
        if (ch + 1 < NCH) {
            const float* Xn = Xp + (ch + 1) * KC;
            const float* Wn = Wp + (size_t)(ch + 1) * KC * NSUM;
            #pragma unroll
            for (int j = 0; j < 4; j++)
                pa[j] = *reinterpret_cast<const float4*>(Xn + (size_t)(ar + 32 * j) * NIN + ac);
            #pragma unroll
            for (int j = 0; j < 2; j++)
                pb[j] = *reinterpret_cast<const float4*>(Wn + (size_t)(br + 16 * j) * NSUM + bc);
        }

        // MMA over this chunk (two k16 steps), fragments via ldmatrix
        const uint32_t abase = As0 + (uint32_t)(buf * BDIM * APITCH * 2);
        const uint32_t bbase = Bs0 + (uint32_t)(buf * KC * BPITCH * 2);
        #pragma unroll
        for (int ks = 0; ks < 2; ks++) {
            unsigned afr[2][4];
            #pragma unroll
            for (int mf = 0; mf < 2; mf++) {
                // rows wm*32 + mf*16 + {0..15}, k cols ks*16 + {0,8}
                const uint32_t addr = abase + aln
                    + (uint32_t)(mf * 16 * APITCH * 2) + (uint32_t)(ks * 32);
                asm volatile(
                    "ldmatrix.sync.aligned.m8n8.x4.shared.b16 {%0,%1,%2,%3}, [%4];"
                    : "=r"(afr[mf][0]), "=r"(afr[mf][1]),
                      "=r"(afr[mf][2]), "=r"(afr[mf][3])
                    : "r"(addr));
            }
            unsigned bfr[2][4];   // [npair]{b0(n0-7), b1(n0-7), b0(n8-15), b1(n8-15)}
            #pragma unroll
            for (int np = 0; np < 2; np++) {
                // rows ks*16 + {0..15}, n cols wn*32 + np*16 + {0,8}
                const uint32_t addr = bbase + bln
                    + (uint32_t)(ks * 16 * BPITCH * 2) + (uint32_t)(np * 32);
                asm volatile(
                    "ldmatrix.sync.aligned.m8n8.x4.trans.shared.b16 {%0,%1,%2,%3}, [%4];"
                    : "=r"(bfr[np][0]), "=r"(bfr[np][1]),
                      "=r"(bfr[np][2]), "=r"(bfr[np][3])
                    : "r"(addr));
            }
            #pragma unroll
            for (int mf = 0; mf < 2; mf++)
                #pragma unroll
                for (int nf = 0; nf < 4; nf++) {
                    const int np = nf >> 1, sel = (nf & 1) * 2;
                    asm volatile(
                        "mma.sync.aligned.m16n8k16.row.col.f32.bf16.bf16.f32 "
                        "{%0,%1,%2,%3}, {%4,%5,%6,%7}, {%8,%9}, {%0,%1,%2,%3};\n"
                        : "+f"(acc[mf][nf][0]), "+f"(acc[mf][nf][1]),
                          "+f"(acc[mf][nf][2]), "+f"(acc[mf][nf][3])
                        : "r"(afr[mf][0]), "r"(afr[mf][1]),
                          "r"(afr[mf][2]), "r"(afr[mf][3]),
                          "r"(bfr[np][sel]), "r"(bfr[np][sel + 1]));
                }
        }
        // double-buffered: the barrier above already protects buf^1 for next iter's STS
    }

    // reduce per-thread column sums (threads sharing bc cover disjoint n rows)
    atomicAdd(&csums[bc + 0], csum[0]);
    atomicAdd(&csums[bc + 1], csum[1]);
    atomicAdd(&csums[bc + 2], csum[2]);
    atomicAdd(&csums[bc + 3], csum[3]);
    __syncthreads();

    // epilogue: out = log(P) - log(C[col])
    const int g = lane >> 2, q = lane & 3;
    #pragma unroll
    for (int nf = 0; nf < 4; nf++) {
        const int c = wn * 32 + nf * 8 + q * 2;
        const float lc0 = __logf(csums[c]);
        const float lc1 = __logf(csums[c + 1]);
        #pragma unroll
        for (int mf = 0; mf < 2; mf++) {
            const int r0 = wm * 32 + mf * 16 + g;
            Op[(size_t)r0 * NSUM + c]           = __logf(acc[mf][nf][0]) - lc0;
            Op[(size_t)r0 * NSUM + c + 1]       = __logf(acc[mf][nf][1]) - lc1;
            Op[(size_t)(r0 + 8) * NSUM + c]     = __logf(acc[mf][nf][2]) - lc0;
            Op[(size_t)(r0 + 8) * NSUM + c + 1] = __logf(acc[mf][nf][3]) - lc1;
        }
    }
}

extern "C" void kernel_launch(void* const* d_in, const int* in_sizes, int n_in,
                              void* d_out, int out_size)
{
    const float* x    = (const float*)d_in[0];
    const float* accs = (const float*)d_in[1];
    if (n_in >= 2 && in_sizes[0] > in_sizes[1]) {   // defensive order check
        const float* tmp = x; x = accs; accs = tmp;
    }
    dim3 grid(NSUM / NT, NSD);   // (8, 256)
    densesum_kernel<<<grid, 256>>>(x, accs, (float*)d_out);
}